// round 10
// baseline (speedup 1.0000x reference)
#include <cuda_runtime.h>
#include <math.h>

#define NN 20000
#define EE 320000
#define NEL 10
#define BUCKET 128

typedef unsigned long long u64;

// ---------------- f32x2 helpers (Blackwell packed fp32) ----------------
__device__ __forceinline__ u64 pk2(float v) {
    u64 r; asm("mov.b64 %0, {%1, %1};" : "=l"(r) : "f"(v)); return r;
}
__device__ __forceinline__ u64 fma2(u64 a, u64 b, u64 c) {
    u64 d; asm("fma.rn.f32x2 %0, %1, %2, %3;" : "=l"(d) : "l"(a), "l"(b), "l"(c)); return d;
}
__device__ __forceinline__ float2 u2f(u64 v) {
    float2 o; asm("mov.b64 {%0, %1}, %2;" : "=f"(o.x), "=f"(o.y) : "l"(v)); return o;
}
__device__ __forceinline__ float silu(float x) { return x / (1.0f + expf(-x)); }

// ---------------- scratch (static device globals; no allocation) ----------------
__device__ __align__(256) float g_Y[EE * 16];
__device__ __align__(256) float g_eb[EE * 8];
__device__ __align__(256) float g_R[(size_t)EE * 128];
__device__ __align__(256) float g_Re[(size_t)2 * EE * 32];   // per-layer Re
__device__ __align__(256) float g_nfA[NN * 512];
__device__ __align__(256) float g_nfB[NN * 512];
__device__ __align__(256) float g_h0[NN * 32];
__device__ int   g_cnt[NN];
__device__ int   g_bucket[NN * BUCKET];
__device__ __align__(256) float g_ncs0[NN * 100];
__device__ __align__(256) float g_ncs1[NN * 100];

__device__ constexpr int OF[16] = {0,1,1,1,2,2,2,2,2,3,3,3,3,3,3,3};

// ---------------- setup kernels ----------------
__global__ void k_zero() {
    int i = blockIdx.x * 256 + threadIdx.x;
    if (i < NN) g_cnt[i] = 0;
}

__global__ void k_geom(const float* __restrict__ pos, const float* __restrict__ shifts,
                       const int* __restrict__ ei) {
    int e = blockIdx.x * 256 + threadIdx.x;
    if (e >= EE) return;
    int src = ei[e], dst = ei[EE + e];
    float vx = pos[dst*3+0] - pos[src*3+0] + shifts[e*3+0];
    float vy = pos[dst*3+1] - pos[src*3+1] + shifts[e*3+1];
    float vz = pos[dst*3+2] - pos[src*3+2] + shifts[e*3+2];
    float r = sqrtf(vx*vx + vy*vy + vz*vz) + 1e-9f;
    float inv = 1.0f / r;
    float x = vx*inv, y = vy*inv, z = vz*inv;
    const float s3 = 1.7320508075688772f, s5 = 2.23606797749979f;
    const float s15 = 3.872983346207417f, s7 = 2.6457513110645907f;
    const float c358 = 2.091650066335189f, c105 = 10.246950765959598f, c218 = 1.6201851746019651f;
    float z2 = z*z, x2 = x*x, y2 = y*y;
    float4* Yo = (float4*)(g_Y + e*16);
    Yo[0] = make_float4(1.0f, s3*x, s3*y, s3*z);
    Yo[1] = make_float4(s15*x*y, s15*y*z, 0.5f*s5*(3.0f*z2-1.0f), s15*x*z);
    Yo[2] = make_float4(0.5f*s15*(x2-y2), c358*y*(3.0f*x2-y2), c105*x*y*z,
                        c218*y*(5.0f*z2-1.0f));
    Yo[3] = make_float4(0.5f*s7*z*(5.0f*z2-3.0f), c218*x*(5.0f*z2-1.0f),
                        0.5f*c105*z*(x2-y2), c358*x*(x2-3.0f*y2));
    // bessel * polynomial cutoff (P=5)
    float xr = r * 0.2f;
    float fc = 0.0f;
    if (xr < 1.0f) {
        float p2 = xr*xr, p4 = p2*p2, p5 = p4*xr;
        fc = 1.0f - 21.0f*p5 + 35.0f*p5*xr - 15.0f*p5*p2;
    }
    float s = 0.6324555320336759f * inv * fc;
    // accurate sinf per harmonic (matches reference jnp.sin)
    float eb[8];
    #pragma unroll
    for (int n = 1; n <= 8; n++)
        eb[n-1] = s * sinf((float)n * 0.6283185307179586f * r);
    float4* ebo = (float4*)(g_eb + e*8);
    ebo[0] = make_float4(eb[0], eb[1], eb[2], eb[3]);
    ebo[1] = make_float4(eb[4], eb[5], eb[6], eb[7]);
    // bucket scatter (dst)
    int p = atomicAdd(&g_cnt[dst], 1);
    if (p < BUCKET) g_bucket[dst*BUCKET + p] = e;
}

__global__ void k_sort() {  // deterministic order: per-node insertion sort by edge id
    int n = blockIdx.x * 128 + threadIdx.x;
    if (n >= NN) return;
    int deg = g_cnt[n]; if (deg > BUCKET) deg = BUCKET;
    int* b = g_bucket + n*BUCKET;
    for (int i = 1; i < deg; i++) {
        int v = b[i]; int j = i - 1;
        while (j >= 0 && b[j] > v) { b[j+1] = b[j]; j--; }
        b[j+1] = v;
    }
}

__global__ void k_init(const float* __restrict__ W_emb, const int* __restrict__ nt) {
    int idx = blockIdx.x * 256 + threadIdx.x;   // float4 index
    if (idx >= NN * 128) return;
    int n = idx >> 7, rem = idx & 127, c = rem >> 2, l4 = rem & 3;
    float4 v = make_float4(0.0f, 0.0f, 0.0f, 0.0f);
    if (l4 == 0) v.x = W_emb[nt[n]*32 + c];
    ((float4*)g_nfA)[idx] = v;
}

// ---------------- per-layer kernels ----------------
__global__ void k_h0(const float* __restrict__ W_up, int t, int flip) {
    int w = threadIdx.x >> 5, lane = threadIdx.x & 31;
    int n = blockIdx.x * 4 + w;
    if (n >= NN) return;
    const float* nfin = flip ? g_nfB : g_nfA;
    const float* nf0 = nfin + n*512;
    const float* W = W_up + t*1024;
    float a = 0.0f;
    #pragma unroll
    for (int c = 0; c < 32; c++) a += nf0[c*16] * W[c*32 + lane];
    g_h0[n*32 + lane] = a;
}

// fused radial MLP: eb -> silu(W1) -> silu(W2) -> W3 -> R ; plus Re = silu(eb@W_er)
// one edge per thread, f32x2-packed over output-channel pairs.
// FULL UNROLL on all loops touching register arrays (x1s/x2s) — partial unroll
// demotes them to local memory. Accumulators split into halves/quarters to cap regs.
__global__ void __launch_bounds__(128) k_radial(
        const float* __restrict__ rW1, const float* __restrict__ rb1,
        const float* __restrict__ rW2, const float* __restrict__ rb2,
        const float* __restrict__ rW3, const float* __restrict__ W_er, int t) {
    extern __shared__ float sw[];
    float* s_w1  = sw;            // 512
    float* s_b1  = sw + 512;      // 64
    float* s_w2  = sw + 576;      // 4096  (16B-aligned: 576*4=2304)
    float* s_b2  = sw + 4672;     // 64
    float* s_w3  = sw + 4736;     // 8192  (16B-aligned: 4736*4=18944)
    float* s_wer = sw + 12928;    // 256   -> total 13184 floats = 52736 B
    int tid = threadIdx.x;
    for (int i = tid; i < 512;  i += 128) s_w1[i]  = rW1[t*512 + i];
    for (int i = tid; i < 4096; i += 128) s_w2[i]  = rW2[t*4096 + i];
    for (int i = tid; i < 8192; i += 128) s_w3[i]  = rW3[t*8192 + i];
    for (int i = tid; i < 256;  i += 128) s_wer[i] = W_er[t*256 + i];
    if (tid < 64) { s_b1[tid] = rb1[t*64 + tid]; s_b2[tid] = rb2[t*64 + tid]; }
    __syncthreads();

    int e = blockIdx.x * 128 + tid;
    float4 ebA = *(const float4*)&g_eb[e*8];
    float4 ebB = *(const float4*)&g_eb[e*8 + 4];
    u64 ebp[8];
    ebp[0] = pk2(ebA.x); ebp[1] = pk2(ebA.y); ebp[2] = pk2(ebA.z); ebp[3] = pk2(ebA.w);
    ebp[4] = pk2(ebB.x); ebp[5] = pk2(ebB.y); ebp[6] = pk2(ebB.z); ebp[7] = pk2(ebB.w);

    // ---- Re = silu(eb @ W_er) : 8 -> 32 (early, so ebp dies after layer 1) ----
    float* ReOut = g_Re + (size_t)t * EE * 32;
    const u64* werp = (const u64*)s_wer;
    #pragma unroll
    for (int cp = 0; cp < 16; cp++) {
        u64 acc = 0ull;
        #pragma unroll
        for (int b = 0; b < 8; b++) acc = fma2(ebp[b], werp[b*16 + cp], acc);
        float2 v = u2f(acc);
        float2 o; o.x = silu(v.x); o.y = silu(v.y);
        *(float2*)&ReOut[e*32 + 2*cp] = o;
    }

    // ---- layer 1: 8 -> 64, silu ----
    float x1s[64];
    const u64* w1p = (const u64*)s_w1;
    #pragma unroll
    for (int jp = 0; jp < 32; jp++) {
        u64 acc = *(const u64*)&s_b1[2*jp];
        #pragma unroll
        for (int b = 0; b < 8; b++) acc = fma2(ebp[b], w1p[b*32 + jp], acc);
        float2 v = u2f(acc);
        x1s[2*jp]   = silu(v.x);
        x1s[2*jp+1] = silu(v.y);
    }

    // ---- layer 2: 64 -> 64, silu; two 32-output halves (a2[16] = 32 regs) ----
    float x2s[64];
    const ulonglong2* w2p = (const ulonglong2*)s_w2;
    #pragma unroll
    for (int h2 = 0; h2 < 2; h2++) {
        u64 a2[16];
        #pragma unroll
        for (int q = 0; q < 16; q++) a2[q] = *(const u64*)&s_b2[h2*32 + 2*q];
        #pragma unroll
        for (int i = 0; i < 64; i++) {
            u64 bc = pk2(x1s[i]);
            #pragma unroll
            for (int q = 0; q < 8; q++) {
                ulonglong2 wv = w2p[i*16 + h2*8 + q];
                a2[2*q]   = fma2(bc, wv.x, a2[2*q]);
                a2[2*q+1] = fma2(bc, wv.y, a2[2*q+1]);
            }
        }
        #pragma unroll
        for (int q = 0; q < 16; q++) {
            float2 v = u2f(a2[q]);
            x2s[h2*32 + 2*q]     = silu(v.x);
            x2s[h2*32 + 2*q + 1] = silu(v.y);
        }
    }

    // ---- layer 3: 64 -> 128 (no act); four 32-output quarters (a3[16]) ----
    float* Rp = g_R + (size_t)e * 128;
    const ulonglong2* w3p = (const ulonglong2*)s_w3;
    #pragma unroll
    for (int h = 0; h < 4; h++) {
        u64 a3[16];
        #pragma unroll
        for (int q = 0; q < 16; q++) a3[q] = 0ull;
        #pragma unroll
        for (int i = 0; i < 64; i++) {
            u64 bc = pk2(x2s[i]);
            #pragma unroll
            for (int q = 0; q < 8; q++) {
                ulonglong2 wv = w3p[i*32 + h*8 + q];
                a3[2*q]   = fma2(bc, wv.x, a3[2*q]);
                a3[2*q+1] = fma2(bc, wv.y, a3[2*q+1]);
            }
        }
        #pragma unroll
        for (int q = 0; q < 8; q++) {
            ulonglong2 st; st.x = a3[2*q]; st.y = a3[2*q+1];
            *(ulonglong2*)&Rp[h*32 + 4*q] = st;
        }
    }
}

// fused per-node: gather/agg -> m -> sc -> pf -> nf_new -> node head (8 nodes/block)
__global__ void k_node(const float* __restrict__ W_lmix, const float* __restrict__ W_scm,
                       const float* __restrict__ W_hid, const float* __restrict__ gsc,
                       const float* __restrict__ W_prod, const float* __restrict__ W_node,
                       const int* __restrict__ ei, const int* __restrict__ ntypes,
                       int t, int flip) {
    extern __shared__ float sm[];
    float* s_lmix = sm;                 // 4096
    float* s_scm  = sm + 4096;          // 4096
    float* s_hid  = sm + 8192;          // 4096
    float* s_buf  = sm + 12288;         // 8 warps * 512
    float* s_q    = sm + 12288 + 4096;  // 8 warps * 32
    int tid = threadIdx.x;
    for (int i = tid; i < 4096; i += 256) {
        s_lmix[i] = W_lmix[t*4096 + i];
        s_scm[i]  = W_scm[t*4096 + i];
        s_hid[i]  = W_hid[t*4096 + i];
    }
    __syncthreads();
    int w = tid >> 5, lane = tid & 31;
    int n = blockIdx.x * 8 + w;
    if (n >= NN) return;
    const float* nfin = flip ? g_nfB : g_nfA;
    float* nfout = flip ? g_nfA : g_nfB;
    float* ncs = t ? g_ncs1 : g_ncs0;
    float* sb = s_buf + w*512;

    // phase A: gather aggregation (lane = channel c).
    float acc[16];
    #pragma unroll
    for (int l = 0; l < 16; l++) acc[l] = 0.0f;
    int deg = g_cnt[n]; if (deg > BUCKET) deg = BUCKET;
    const int* bk = g_bucket + n*BUCKET;
    int eReg[4], sReg[4];
    #pragma unroll
    for (int q = 0; q < 4; q++) {
        int idx = q*32 + lane;
        int ev = (idx < deg) ? bk[idx] : 0;
        eReg[q] = ev;
        sReg[q] = (idx < deg) ? ei[ev] : 0;
    }
    #pragma unroll
    for (int q = 0; q < 4; q++) {
        int lim = deg - q*32;
        if (lim <= 0) break;
        if (lim > 32) lim = 32;
        for (int sl = 0; sl < lim; sl++) {
            int e   = __shfl_sync(0xFFFFFFFFu, eReg[q], sl);
            int src = __shfl_sync(0xFFFFFFFFu, sReg[q], sl);
            float h = g_h0[src*32 + lane];
            const float* Rp = g_R + (size_t)e * 128;
            float r0 = Rp[lane]*h, r1 = Rp[32+lane]*h, r2 = Rp[64+lane]*h, r3 = Rp[96+lane]*h;
            const float4* Yv = (const float4*)(g_Y + e*16);
            float4 y0 = Yv[0], y1 = Yv[1], y2 = Yv[2], y3 = Yv[3];
            acc[0]  += r0*y0.x;
            acc[1]  += r1*y0.y;  acc[2]  += r1*y0.z;  acc[3]  += r1*y0.w;
            acc[4]  += r2*y1.x;  acc[5]  += r2*y1.y;  acc[6]  += r2*y1.z;
            acc[7]  += r2*y1.w;  acc[8]  += r2*y2.x;
            acc[9]  += r3*y2.y;  acc[10] += r3*y2.z;  acc[11] += r3*y2.w;
            acc[12] += r3*y3.x;  acc[13] += r3*y3.y;  acc[14] += r3*y3.z;
            acc[15] += r3*y3.w;
        }
    }
    #pragma unroll
    for (int l = 0; l < 16; l++) sb[l*32 + lane] = acc[l] * 0.0625f;
    __syncwarp();

    // phase B: m = agg mixed by W_lmix (lane = output k)
    float m[16];
    #pragma unroll
    for (int l = 0; l < 16; l++) {
        const float* wp = s_lmix + OF[l]*1024;
        float a = 0.0f;
        #pragma unroll
        for (int c = 0; c < 32; c++) a += sb[l*32 + c] * wp[c*32 + lane];
        m[l] = a;
    }
    __syncwarp();

    // phase C: sc from old nf (transpose into sb, then mix by W_scm * g_sc)
    {
        const float* nfo = nfin + n*512 + lane*16;
        float4 v0 = ((const float4*)nfo)[0];
        float4 v1 = ((const float4*)nfo)[1];
        float4 v2 = ((const float4*)nfo)[2];
        float4 v3 = ((const float4*)nfo)[3];
        sb[0*32+lane]=v0.x;  sb[1*32+lane]=v0.y;  sb[2*32+lane]=v0.z;  sb[3*32+lane]=v0.w;
        sb[4*32+lane]=v1.x;  sb[5*32+lane]=v1.y;  sb[6*32+lane]=v1.z;  sb[7*32+lane]=v1.w;
        sb[8*32+lane]=v2.x;  sb[9*32+lane]=v2.y;  sb[10*32+lane]=v2.z; sb[11*32+lane]=v2.w;
        sb[12*32+lane]=v3.x; sb[13*32+lane]=v3.y; sb[14*32+lane]=v3.z; sb[15*32+lane]=v3.w;
    }
    __syncwarp();
    int ty = ntypes[n];
    float g = gsc[t*NEL*32 + ty*32 + lane];
    float sc[16];
    #pragma unroll
    for (int l = 0; l < 16; l++) {
        const float* wp = s_scm + OF[l]*1024;
        float a = 0.0f;
        #pragma unroll
        for (int c = 0; c < 32; c++) a += sb[l*32 + c] * wp[c*32 + lane];
        sc[l] = a * g;
    }
    __syncwarp();

    // phase D: pf (lane = channel c)
    const float* wpp = W_prod + t*NEL*96 + ty*96;
    float w0 = wpp[lane], w1 = wpp[32+lane], w2 = wpp[64+lane];
    float s0 = m[0];
    float f = w0 + s0*w1 + s0*s0*w2;
    #pragma unroll
    for (int l = 0; l < 16; l++) sb[l*32 + lane] = m[l] * f;
    __syncwarp();

    // phase E: nf_new (lane = output k)
    float nfn[16];
    #pragma unroll
    for (int l = 0; l < 16; l++) {
        const float* wp = s_hid + OF[l]*1024;
        float a = 0.0f;
        #pragma unroll
        for (int c = 0; c < 32; c++) a += sb[l*32 + c] * wp[c*32 + lane];
        nfn[l] = a + sc[l];
    }
    float* nout = nfout + n*512 + lane*16;
    ((float4*)nout)[0] = make_float4(nfn[0],  nfn[1],  nfn[2],  nfn[3]);
    ((float4*)nout)[1] = make_float4(nfn[4],  nfn[5],  nfn[6],  nfn[7]);
    ((float4*)nout)[2] = make_float4(nfn[8],  nfn[9],  nfn[10], nfn[11]);
    ((float4*)nout)[3] = make_float4(nfn[12], nfn[13], nfn[14], nfn[15]);

    // phase F: node head (new nf L=0 @ W_node)
    s_q[w*32 + lane] = nfn[0];
    __syncwarp();
    const float* Wn = W_node + t*3200;
    for (int j = lane; j < 100; j += 32) {
        float a = 0.0f;
        #pragma unroll
        for (int c = 0; c < 32; c++) a += s_q[w*32 + c] * Wn[c*100 + j];
        ncs[n*100 + j] = a;
    }
}

// ---------------- output assembly ----------------
// out layout: [node_sum N*100][node_contrib N*100*2][edge_sum E*100][edge_contrib E*100*2]
__global__ void k_fin_node(float* __restrict__ out) {
    int i2 = blockIdx.x * 256 + threadIdx.x;   // pair index
    if (i2 >= NN * 50) return;
    float2 a = *(const float2*)&g_ncs0[2*i2];
    float2 b = *(const float2*)&g_ncs1[2*i2];
    *(float2*)&out[2*i2] = make_float2(a.x + b.x, a.y + b.y);
    *(float4*)&out[2000000 + 4*i2] = make_float4(a.x, b.x, a.y, b.y);
}

// fused edge head, both layers: invariant q = Re * <nf_src+nf_dst, Y> computed
// directly from the live nf buffers (layer0 -> g_nfB, layer1 -> g_nfA), then
// 32->100 projection + sum + interleaved contrib. Warp per edge; f32x2 pairs.
__global__ void k_fin_edge(const float* __restrict__ W_edge, const int* __restrict__ ei,
                           float* __restrict__ out) {
    __shared__ float s_we[6528];   // 2*3200 used, padded
    int tid = threadIdx.x;
    for (int i = tid; i < 6400; i += 256) s_we[i] = W_edge[i];  // [t][c][j]
    __syncthreads();
    int w = tid >> 5, lane = tid & 31;
    int e = blockIdx.x * 8 + w;
    int src = ei[e], dst = ei[EE + e];
    const float4* Yv = (const float4*)(g_Y + e*16);
    float4 y0 = Yv[0], y1 = Yv[1], y2 = Yv[2], y3 = Yv[3];

    float inv0, inv1;
    {   // layer 0 output lives in g_nfB
        const float* ns = g_nfB + src*512 + lane*16;
        const float* nd = g_nfB + dst*512 + lane*16;
        float4 a0 = ((const float4*)ns)[0], b0 = ((const float4*)nd)[0];
        float4 a1 = ((const float4*)ns)[1], b1 = ((const float4*)nd)[1];
        float4 a2 = ((const float4*)ns)[2], b2 = ((const float4*)nd)[2];
        float4 a3 = ((const float4*)ns)[3], b3 = ((const float4*)nd)[3];
        float iv = 0.0f;
        iv += (a0.x+b0.x)*y0.x + (a0.y+b0.y)*y0.y + (a0.z+b0.z)*y0.z + (a0.w+b0.w)*y0.w;
        iv += (a1.x+b1.x)*y1.x + (a1.y+b1.y)*y1.y + (a1.z+b1.z)*y1.z + (a1.w+b1.w)*y1.w;
        iv += (a2.x+b2.x)*y2.x + (a2.y+b2.y)*y2.y + (a2.z+b2.z)*y2.z + (a2.w+b2.w)*y2.w;
        iv += (a3.x+b3.x)*y3.x + (a3.y+b3.y)*y3.y + (a3.z+b3.z)*y3.z + (a3.w+b3.w)*y3.w;
        inv0 = iv;
    }
    {   // layer 1 output lives in g_nfA
        const float* ns = g_nfA + src*512 + lane*16;
        const float* nd = g_nfA + dst*512 + lane*16;
        float4 a0 = ((const float4*)ns)[0], b0 = ((const float4*)nd)[0];
        float4 a1 = ((const float4*)ns)[1], b1 = ((const float4*)nd)[1];
        float4 a2 = ((const float4*)ns)[2], b2 = ((const float4*)nd)[2];
        float4 a3 = ((const float4*)ns)[3], b3 = ((const float4*)nd)[3];
        float iv = 0.0f;
        iv += (a0.x+b0.x)*y0.x + (a0.y+b0.y)*y0.y + (a0.z+b0.z)*y0.z + (a0.w+b0.w)*y0.w;
        iv += (a1.x+b1.x)*y1.x + (a1.y+b1.y)*y1.y + (a1.z+b1.z)*y1.z + (a1.w+b1.w)*y1.w;
        iv += (a2.x+b2.x)*y2.x + (a2.y+b2.y)*y2.y + (a2.z+b2.z)*y2.z + (a2.w+b2.w)*y2.w;
        iv += (a3.x+b3.x)*y3.x + (a3.y+b3.y)*y3.y + (a3.z+b3.z)*y3.z + (a3.w+b3.w)*y3.w;
        inv1 = iv;
    }
    float q0 = inv0 * g_Re[(size_t)e*32 + lane];
    float q1 = inv1 * g_Re[(size_t)EE*32 + (size_t)e*32 + lane];

    u64 a00 = 0ull, a01 = 0ull, a10 = 0ull, a11 = 0ull;
    #pragma unroll
    for (int c = 0; c < 32; c++) {
        u64 b0 = pk2(__shfl_sync(0xFFFFFFFFu, q0, c));
        u64 b1 = pk2(__shfl_sync(0xFFFFFFFFu, q1, c));
        const u64* w0 = (const u64*)&s_we[c*100];
        const u64* w1 = (const u64*)&s_we[3200 + c*100];
        a00 = fma2(b0, w0[lane], a00);
        a10 = fma2(b1, w1[lane], a10);
        if (lane < 18) {
            a01 = fma2(b0, w0[lane + 32], a01);
            a11 = fma2(b1, w1[lane + 32], a11);
        }
    }
    // pair p = lane  (outputs j = 2p, 2p+1)
    {
        float2 v0 = u2f(a00), v1 = u2f(a10);
        *(float2*)&out[6000000 + e*100 + 2*lane] = make_float2(v0.x + v1.x, v0.y + v1.y);
        *(float4*)&out[38000000 + e*200 + 4*lane] = make_float4(v0.x, v1.x, v0.y, v1.y);
    }
    // pair p = lane+32 (outputs j = 64+2*lane, 65+2*lane) for lane < 18
    if (lane < 18) {
        float2 v0 = u2f(a01), v1 = u2f(a11);
        *(float2*)&out[6000000 + e*100 + 64 + 2*lane] = make_float2(v0.x + v1.x, v0.y + v1.y);
        *(float4*)&out[38000000 + e*200 + 128 + 4*lane] = make_float4(v0.x, v1.x, v0.y, v1.y);
    }
}

// ---------------- launch ----------------
extern "C" void kernel_launch(void* const* d_in, const int* in_sizes, int n_in,
                              void* d_out, int out_size) {
    const float* positions = (const float*)d_in[0];
    const float* shifts    = (const float*)d_in[2];
    const float* W_emb     = (const float*)d_in[3];
    const float* rW1       = (const float*)d_in[4];
    const float* rb1       = (const float*)d_in[5];
    const float* rW2       = (const float*)d_in[6];
    const float* rb2       = (const float*)d_in[7];
    const float* rW3       = (const float*)d_in[8];
    const float* W_up      = (const float*)d_in[9];
    const float* W_lmix    = (const float*)d_in[10];
    const float* W_scm     = (const float*)d_in[11];
    const float* gsc       = (const float*)d_in[12];
    const float* W_prod    = (const float*)d_in[13];
    const float* W_hid     = (const float*)d_in[14];
    const float* W_node    = (const float*)d_in[15];
    const float* W_edge    = (const float*)d_in[16];
    const float* W_er      = (const float*)d_in[17];
    const int*   ei        = (const int*)d_in[18];
    const int*   nt        = (const int*)d_in[19];
    float* out = (float*)d_out;

    cudaFuncSetAttribute(k_radial, cudaFuncAttributeMaxDynamicSharedMemorySize, 52736);
    cudaFuncSetAttribute(k_node,   cudaFuncAttributeMaxDynamicSharedMemorySize, 66560);

    k_zero<<<(NN + 255) / 256, 256>>>();
    k_geom<<<EE / 256, 256>>>(positions, shifts, ei);
    k_sort<<<(NN + 127) / 128, 128>>>();
    k_init<<<(NN * 128 + 255) / 256, 256>>>(W_emb, nt);

    for (int t = 0; t < 2; t++) {
        int flip = t;
        k_h0<<<NN / 4, 128>>>(W_up, t, flip);
        k_radial<<<EE / 128, 128, 52736>>>(rW1, rb1, rW2, rb2, rW3, W_er, t);
        k_node<<<NN / 8, 256, 66560>>>(W_lmix, W_scm, W_hid, gsc, W_prod, W_node,
                                       ei, nt, t, flip);
    }
    k_fin_node<<<(NN * 50 + 255) / 256, 256>>>(out);
    k_fin_edge<<<EE / 8, 256>>>(W_edge, ei, out);
}

// round 11
// speedup vs baseline: 1.6834x; 1.6834x over previous
#include <cuda_runtime.h>
#include <math.h>

#define NN 20000
#define EE 320000
#define NEL 10
#define BUCKET 128

typedef unsigned long long u64;

// ---------------- f32x2 helpers (Blackwell packed fp32) ----------------
__device__ __forceinline__ u64 pk2(float v) {
    u64 r; asm("mov.b64 %0, {%1, %1};" : "=l"(r) : "f"(v)); return r;
}
__device__ __forceinline__ u64 fma2(u64 a, u64 b, u64 c) {
    u64 d; asm("fma.rn.f32x2 %0, %1, %2, %3;" : "=l"(d) : "l"(a), "l"(b), "l"(c)); return d;
}
__device__ __forceinline__ float2 u2f(u64 v) {
    float2 o; asm("mov.b64 {%0, %1}, %2;" : "=f"(o.x), "=f"(o.y) : "l"(v)); return o;
}
__device__ __forceinline__ float silu(float x) { return x / (1.0f + expf(-x)); }

// ---------------- scratch (static device globals; no allocation) ----------------
__device__ __align__(256) float g_Y[EE * 16];
__device__ __align__(256) float g_eb[EE * 8];
__device__ __align__(256) float g_R[(size_t)EE * 128];
__device__ __align__(256) float g_Re[(size_t)2 * EE * 32];   // per-layer Re
__device__ __align__(256) float g_nfA[NN * 512];
__device__ __align__(256) float g_nfB[NN * 512];
__device__ __align__(256) float g_h0[NN * 32];
__device__ int   g_cnt[NN];
__device__ int   g_bucket[NN * BUCKET];
__device__ __align__(256) float g_ncs0[NN * 100];
__device__ __align__(256) float g_ncs1[NN * 100];

__device__ constexpr int OF[16] = {0,1,1,1,2,2,2,2,2,3,3,3,3,3,3,3};

// ---------------- setup kernels ----------------
__global__ void k_zero() {
    int i = blockIdx.x * 256 + threadIdx.x;
    if (i < NN) g_cnt[i] = 0;
}

__global__ void k_geom(const float* __restrict__ pos, const float* __restrict__ shifts,
                       const int* __restrict__ ei) {
    int e = blockIdx.x * 256 + threadIdx.x;
    if (e >= EE) return;
    int src = ei[e], dst = ei[EE + e];
    float vx = pos[dst*3+0] - pos[src*3+0] + shifts[e*3+0];
    float vy = pos[dst*3+1] - pos[src*3+1] + shifts[e*3+1];
    float vz = pos[dst*3+2] - pos[src*3+2] + shifts[e*3+2];
    float r = sqrtf(vx*vx + vy*vy + vz*vz) + 1e-9f;
    float inv = 1.0f / r;
    float x = vx*inv, y = vy*inv, z = vz*inv;
    const float s3 = 1.7320508075688772f, s5 = 2.23606797749979f;
    const float s15 = 3.872983346207417f, s7 = 2.6457513110645907f;
    const float c358 = 2.091650066335189f, c105 = 10.246950765959598f, c218 = 1.6201851746019651f;
    float z2 = z*z, x2 = x*x, y2 = y*y;
    float4* Yo = (float4*)(g_Y + e*16);
    Yo[0] = make_float4(1.0f, s3*x, s3*y, s3*z);
    Yo[1] = make_float4(s15*x*y, s15*y*z, 0.5f*s5*(3.0f*z2-1.0f), s15*x*z);
    Yo[2] = make_float4(0.5f*s15*(x2-y2), c358*y*(3.0f*x2-y2), c105*x*y*z,
                        c218*y*(5.0f*z2-1.0f));
    Yo[3] = make_float4(0.5f*s7*z*(5.0f*z2-3.0f), c218*x*(5.0f*z2-1.0f),
                        0.5f*c105*z*(x2-y2), c358*x*(x2-3.0f*y2));
    // bessel * polynomial cutoff (P=5)
    float xr = r * 0.2f;
    float fc = 0.0f;
    if (xr < 1.0f) {
        float p2 = xr*xr, p4 = p2*p2, p5 = p4*xr;
        fc = 1.0f - 21.0f*p5 + 35.0f*p5*xr - 15.0f*p5*p2;
    }
    float s = 0.6324555320336759f * inv * fc;
    // accurate sinf per harmonic (matches reference jnp.sin)
    float eb[8];
    #pragma unroll
    for (int n = 1; n <= 8; n++)
        eb[n-1] = s * sinf((float)n * 0.6283185307179586f * r);
    float4* ebo = (float4*)(g_eb + e*8);
    ebo[0] = make_float4(eb[0], eb[1], eb[2], eb[3]);
    ebo[1] = make_float4(eb[4], eb[5], eb[6], eb[7]);
    // bucket scatter (dst)
    int p = atomicAdd(&g_cnt[dst], 1);
    if (p < BUCKET) g_bucket[dst*BUCKET + p] = e;
}

__global__ void k_sort() {  // deterministic order: per-node insertion sort by edge id
    int n = blockIdx.x * 128 + threadIdx.x;
    if (n >= NN) return;
    int deg = g_cnt[n]; if (deg > BUCKET) deg = BUCKET;
    int* b = g_bucket + n*BUCKET;
    for (int i = 1; i < deg; i++) {
        int v = b[i]; int j = i - 1;
        while (j >= 0 && b[j] > v) { b[j+1] = b[j]; j--; }
        b[j+1] = v;
    }
}

__global__ void k_init(const float* __restrict__ W_emb, const int* __restrict__ nt) {
    int idx = blockIdx.x * 256 + threadIdx.x;   // float4 index
    if (idx >= NN * 128) return;
    int n = idx >> 7, rem = idx & 127, c = rem >> 2, l4 = rem & 3;
    float4 v = make_float4(0.0f, 0.0f, 0.0f, 0.0f);
    if (l4 == 0) v.x = W_emb[nt[n]*32 + c];
    ((float4*)g_nfA)[idx] = v;
}

// ---------------- per-layer kernels ----------------
__global__ void k_h0(const float* __restrict__ W_up, int t, int flip) {
    int w = threadIdx.x >> 5, lane = threadIdx.x & 31;
    int n = blockIdx.x * 4 + w;
    if (n >= NN) return;
    const float* nfin = flip ? g_nfB : g_nfA;
    const float* nf0 = nfin + n*512;
    const float* W = W_up + t*1024;
    float a = 0.0f;
    #pragma unroll
    for (int c = 0; c < 32; c++) a += nf0[c*16] * W[c*32 + lane];
    g_h0[n*32 + lane] = a;
}

// fused radial MLP: eb -> silu(W1) -> silu(W2) -> W3 -> R ; plus Re = silu(eb@W_er)
// one edge per thread, f32x2-packed over output-channel pairs.
// (R9-measured version — do not restructure without per-kernel profile data.)
__global__ void __launch_bounds__(128) k_radial(
        const float* __restrict__ rW1, const float* __restrict__ rb1,
        const float* __restrict__ rW2, const float* __restrict__ rb2,
        const float* __restrict__ rW3, const float* __restrict__ W_er, int t) {
    extern __shared__ float sw[];
    float* s_w1  = sw;            // 512
    float* s_b1  = sw + 512;      // 64
    float* s_w2  = sw + 576;      // 4096  (16B-aligned: 576*4=2304)
    float* s_b2  = sw + 4672;     // 64
    float* s_w3  = sw + 4736;     // 8192  (16B-aligned: 4736*4=18944)
    float* s_wer = sw + 12928;    // 256   -> total 13184 floats = 52736 B
    int tid = threadIdx.x;
    for (int i = tid; i < 512;  i += 128) s_w1[i]  = rW1[t*512 + i];
    for (int i = tid; i < 4096; i += 128) s_w2[i]  = rW2[t*4096 + i];
    for (int i = tid; i < 8192; i += 128) s_w3[i]  = rW3[t*8192 + i];
    for (int i = tid; i < 256;  i += 128) s_wer[i] = W_er[t*256 + i];
    if (tid < 64) { s_b1[tid] = rb1[t*64 + tid]; s_b2[tid] = rb2[t*64 + tid]; }
    __syncthreads();

    int e = blockIdx.x * 128 + tid;
    float4 ebA = *(const float4*)&g_eb[e*8];
    float4 ebB = *(const float4*)&g_eb[e*8 + 4];
    float ebv[8] = {ebA.x, ebA.y, ebA.z, ebA.w, ebB.x, ebB.y, ebB.z, ebB.w};
    u64 ebp[8];
    #pragma unroll
    for (int b = 0; b < 8; b++) ebp[b] = pk2(ebv[b]);

    // ---- layer 1: 8 -> 64, silu ----
    float x1s[64];
    const u64* w1p = (const u64*)s_w1;
    #pragma unroll 8
    for (int jp = 0; jp < 32; jp++) {
        u64 acc = *(const u64*)&s_b1[2*jp];
        #pragma unroll
        for (int b = 0; b < 8; b++) acc = fma2(ebp[b], w1p[b*32 + jp], acc);
        float2 v = u2f(acc);
        x1s[2*jp]   = silu(v.x);
        x1s[2*jp+1] = silu(v.y);
    }

    // ---- layer 2: 64 -> 64, silu ----
    u64 acc2[32];
    #pragma unroll
    for (int jq = 0; jq < 32; jq++) acc2[jq] = *(const u64*)&s_b2[2*jq];
    const ulonglong2* w2p = (const ulonglong2*)s_w2;
    #pragma unroll 4
    for (int i = 0; i < 64; i++) {
        u64 bc = pk2(x1s[i]);
        #pragma unroll
        for (int jq = 0; jq < 16; jq++) {
            ulonglong2 wv = w2p[i*16 + jq];
            acc2[2*jq]   = fma2(bc, wv.x, acc2[2*jq]);
            acc2[2*jq+1] = fma2(bc, wv.y, acc2[2*jq+1]);
        }
    }
    float x2s[64];
    #pragma unroll 8
    for (int jq = 0; jq < 32; jq++) {
        float2 v = u2f(acc2[jq]);
        x2s[2*jq]   = silu(v.x);
        x2s[2*jq+1] = silu(v.y);
    }

    // ---- layer 3: 64 -> 128 (no act), two halves for register pressure ----
    float* Rp = g_R + (size_t)e * 128;
    const ulonglong2* w3p = (const ulonglong2*)s_w3;
    #pragma unroll
    for (int h = 0; h < 2; h++) {
        u64 acc3[32];
        #pragma unroll
        for (int q = 0; q < 32; q++) acc3[q] = 0ull;
        #pragma unroll 4
        for (int i = 0; i < 64; i++) {
            u64 bc = pk2(x2s[i]);
            #pragma unroll
            for (int q = 0; q < 16; q++) {
                ulonglong2 wv = w3p[i*32 + h*16 + q];
                acc3[2*q]   = fma2(bc, wv.x, acc3[2*q]);
                acc3[2*q+1] = fma2(bc, wv.y, acc3[2*q+1]);
            }
        }
        #pragma unroll
        for (int q = 0; q < 16; q++) {
            ulonglong2 st; st.x = acc3[2*q]; st.y = acc3[2*q+1];
            *(ulonglong2*)&Rp[h*64 + 4*q] = st;
        }
    }

    // ---- Re = silu(eb @ W_er) : 8 -> 32, per-layer buffer ----
    float* ReOut = g_Re + (size_t)t * EE * 32;
    const u64* werp = (const u64*)s_wer;
    #pragma unroll 4
    for (int cp = 0; cp < 16; cp++) {
        u64 acc = 0ull;
        #pragma unroll
        for (int b = 0; b < 8; b++) acc = fma2(ebp[b], werp[b*16 + cp], acc);
        float2 v = u2f(acc);
        float2 o; o.x = silu(v.x); o.y = silu(v.y);
        *(float2*)&ReOut[e*32 + 2*cp] = o;
    }
}

// fused per-node: gather/agg -> m -> sc -> pf -> nf_new -> node head (8 nodes/block)
__global__ void k_node(const float* __restrict__ W_lmix, const float* __restrict__ W_scm,
                       const float* __restrict__ W_hid, const float* __restrict__ gsc,
                       const float* __restrict__ W_prod, const float* __restrict__ W_node,
                       const int* __restrict__ ei, const int* __restrict__ ntypes,
                       int t, int flip) {
    extern __shared__ float sm[];
    float* s_lmix = sm;                 // 4096
    float* s_scm  = sm + 4096;          // 4096
    float* s_hid  = sm + 8192;          // 4096
    float* s_buf  = sm + 12288;         // 8 warps * 512
    float* s_q    = sm + 12288 + 4096;  // 8 warps * 32
    int tid = threadIdx.x;
    for (int i = tid; i < 4096; i += 256) {
        s_lmix[i] = W_lmix[t*4096 + i];
        s_scm[i]  = W_scm[t*4096 + i];
        s_hid[i]  = W_hid[t*4096 + i];
    }
    __syncthreads();
    int w = tid >> 5, lane = tid & 31;
    int n = blockIdx.x * 8 + w;
    if (n >= NN) return;
    const float* nfin = flip ? g_nfB : g_nfA;
    float* nfout = flip ? g_nfA : g_nfB;
    float* ncs = t ? g_ncs1 : g_ncs0;
    float* sb = s_buf + w*512;

    // phase A: gather aggregation (lane = channel c).
    float acc[16];
    #pragma unroll
    for (int l = 0; l < 16; l++) acc[l] = 0.0f;
    int deg = g_cnt[n]; if (deg > BUCKET) deg = BUCKET;
    const int* bk = g_bucket + n*BUCKET;
    int eReg[4], sReg[4];
    #pragma unroll
    for (int q = 0; q < 4; q++) {
        int idx = q*32 + lane;
        int ev = (idx < deg) ? bk[idx] : 0;
        eReg[q] = ev;
        sReg[q] = (idx < deg) ? ei[ev] : 0;
    }
    #pragma unroll
    for (int q = 0; q < 4; q++) {
        int lim = deg - q*32;
        if (lim <= 0) break;
        if (lim > 32) lim = 32;
        for (int sl = 0; sl < lim; sl++) {
            int e   = __shfl_sync(0xFFFFFFFFu, eReg[q], sl);
            int src = __shfl_sync(0xFFFFFFFFu, sReg[q], sl);
            float h = g_h0[src*32 + lane];
            const float* Rp = g_R + (size_t)e * 128;
            float r0 = Rp[lane]*h, r1 = Rp[32+lane]*h, r2 = Rp[64+lane]*h, r3 = Rp[96+lane]*h;
            const float4* Yv = (const float4*)(g_Y + e*16);
            float4 y0 = Yv[0], y1 = Yv[1], y2 = Yv[2], y3 = Yv[3];
            acc[0]  += r0*y0.x;
            acc[1]  += r1*y0.y;  acc[2]  += r1*y0.z;  acc[3]  += r1*y0.w;
            acc[4]  += r2*y1.x;  acc[5]  += r2*y1.y;  acc[6]  += r2*y1.z;
            acc[7]  += r2*y1.w;  acc[8]  += r2*y2.x;
            acc[9]  += r3*y2.y;  acc[10] += r3*y2.z;  acc[11] += r3*y2.w;
            acc[12] += r3*y3.x;  acc[13] += r3*y3.y;  acc[14] += r3*y3.z;
            acc[15] += r3*y3.w;
        }
    }
    #pragma unroll
    for (int l = 0; l < 16; l++) sb[l*32 + lane] = acc[l] * 0.0625f;
    __syncwarp();

    // phase B: m = agg mixed by W_lmix (lane = output k)
    float m[16];
    #pragma unroll
    for (int l = 0; l < 16; l++) {
        const float* wp = s_lmix + OF[l]*1024;
        float a = 0.0f;
        #pragma unroll
        for (int c = 0; c < 32; c++) a += sb[l*32 + c] * wp[c*32 + lane];
        m[l] = a;
    }
    __syncwarp();

    // phase C: sc from old nf (transpose into sb, then mix by W_scm * g_sc)
    {
        const float* nfo = nfin + n*512 + lane*16;
        float4 v0 = ((const float4*)nfo)[0];
        float4 v1 = ((const float4*)nfo)[1];
        float4 v2 = ((const float4*)nfo)[2];
        float4 v3 = ((const float4*)nfo)[3];
        sb[0*32+lane]=v0.x;  sb[1*32+lane]=v0.y;  sb[2*32+lane]=v0.z;  sb[3*32+lane]=v0.w;
        sb[4*32+lane]=v1.x;  sb[5*32+lane]=v1.y;  sb[6*32+lane]=v1.z;  sb[7*32+lane]=v1.w;
        sb[8*32+lane]=v2.x;  sb[9*32+lane]=v2.y;  sb[10*32+lane]=v2.z; sb[11*32+lane]=v2.w;
        sb[12*32+lane]=v3.x; sb[13*32+lane]=v3.y; sb[14*32+lane]=v3.z; sb[15*32+lane]=v3.w;
    }
    __syncwarp();
    int ty = ntypes[n];
    float g = gsc[t*NEL*32 + ty*32 + lane];
    float sc[16];
    #pragma unroll
    for (int l = 0; l < 16; l++) {
        const float* wp = s_scm + OF[l]*1024;
        float a = 0.0f;
        #pragma unroll
        for (int c = 0; c < 32; c++) a += sb[l*32 + c] * wp[c*32 + lane];
        sc[l] = a * g;
    }
    __syncwarp();

    // phase D: pf (lane = channel c)
    const float* wpp = W_prod + t*NEL*96 + ty*96;
    float w0 = wpp[lane], w1 = wpp[32+lane], w2 = wpp[64+lane];
    float s0 = m[0];
    float f = w0 + s0*w1 + s0*s0*w2;
    #pragma unroll
    for (int l = 0; l < 16; l++) sb[l*32 + lane] = m[l] * f;
    __syncwarp();

    // phase E: nf_new (lane = output k)
    float nfn[16];
    #pragma unroll
    for (int l = 0; l < 16; l++) {
        const float* wp = s_hid + OF[l]*1024;
        float a = 0.0f;
        #pragma unroll
        for (int c = 0; c < 32; c++) a += sb[l*32 + c] * wp[c*32 + lane];
        nfn[l] = a + sc[l];
    }
    float* nout = nfout + n*512 + lane*16;
    ((float4*)nout)[0] = make_float4(nfn[0],  nfn[1],  nfn[2],  nfn[3]);
    ((float4*)nout)[1] = make_float4(nfn[4],  nfn[5],  nfn[6],  nfn[7]);
    ((float4*)nout)[2] = make_float4(nfn[8],  nfn[9],  nfn[10], nfn[11]);
    ((float4*)nout)[3] = make_float4(nfn[12], nfn[13], nfn[14], nfn[15]);

    // phase F: node head (new nf L=0 @ W_node)
    s_q[w*32 + lane] = nfn[0];
    __syncwarp();
    const float* Wn = W_node + t*3200;
    for (int j = lane; j < 100; j += 32) {
        float a = 0.0f;
        #pragma unroll
        for (int c = 0; c < 32; c++) a += s_q[w*32 + c] * Wn[c*100 + j];
        ncs[n*100 + j] = a;
    }
}

// ---------------- output assembly ----------------
// out layout: [node_sum N*100][node_contrib N*100*2][edge_sum E*100][edge_contrib E*100*2]
__global__ void k_fin_node(float* __restrict__ out) {
    int i2 = blockIdx.x * 256 + threadIdx.x;   // pair index
    if (i2 >= NN * 50) return;
    float2 a = *(const float2*)&g_ncs0[2*i2];
    float2 b = *(const float2*)&g_ncs1[2*i2];
    *(float2*)&out[2*i2] = make_float2(a.x + b.x, a.y + b.y);
    *(float4*)&out[2000000 + 4*i2] = make_float4(a.x, b.x, a.y, b.y);
}

// fused edge head, both layers: invariant q = Re * <nf_src+nf_dst, Y> computed
// directly from the live nf buffers (layer0 -> g_nfB, layer1 -> g_nfA), then
// 32->100 projection + sum + interleaved contrib. Warp per edge; f32x2 pairs.
__global__ void k_fin_edge(const float* __restrict__ W_edge, const int* __restrict__ ei,
                           float* __restrict__ out) {
    __shared__ float s_we[6528];   // 2*3200 used, padded
    int tid = threadIdx.x;
    for (int i = tid; i < 6400; i += 256) s_we[i] = W_edge[i];  // [t][c][j]
    __syncthreads();
    int w = tid >> 5, lane = tid & 31;
    int e = blockIdx.x * 8 + w;
    int src = ei[e], dst = ei[EE + e];
    const float4* Yv = (const float4*)(g_Y + e*16);
    float4 y0 = Yv[0], y1 = Yv[1], y2 = Yv[2], y3 = Yv[3];

    float inv0, inv1;
    {   // layer 0 output lives in g_nfB
        const float* ns = g_nfB + src*512 + lane*16;
        const float* nd = g_nfB + dst*512 + lane*16;
        float4 a0 = ((const float4*)ns)[0], b0 = ((const float4*)nd)[0];
        float4 a1 = ((const float4*)ns)[1], b1 = ((const float4*)nd)[1];
        float4 a2 = ((const float4*)ns)[2], b2 = ((const float4*)nd)[2];
        float4 a3 = ((const float4*)ns)[3], b3 = ((const float4*)nd)[3];
        float iv = 0.0f;
        iv += (a0.x+b0.x)*y0.x + (a0.y+b0.y)*y0.y + (a0.z+b0.z)*y0.z + (a0.w+b0.w)*y0.w;
        iv += (a1.x+b1.x)*y1.x + (a1.y+b1.y)*y1.y + (a1.z+b1.z)*y1.z + (a1.w+b1.w)*y1.w;
        iv += (a2.x+b2.x)*y2.x + (a2.y+b2.y)*y2.y + (a2.z+b2.z)*y2.z + (a2.w+b2.w)*y2.w;
        iv += (a3.x+b3.x)*y3.x + (a3.y+b3.y)*y3.y + (a3.z+b3.z)*y3.z + (a3.w+b3.w)*y3.w;
        inv0 = iv;
    }
    {   // layer 1 output lives in g_nfA
        const float* ns = g_nfA + src*512 + lane*16;
        const float* nd = g_nfA + dst*512 + lane*16;
        float4 a0 = ((const float4*)ns)[0], b0 = ((const float4*)nd)[0];
        float4 a1 = ((const float4*)ns)[1], b1 = ((const float4*)nd)[1];
        float4 a2 = ((const float4*)ns)[2], b2 = ((const float4*)nd)[2];
        float4 a3 = ((const float4*)ns)[3], b3 = ((const float4*)nd)[3];
        float iv = 0.0f;
        iv += (a0.x+b0.x)*y0.x + (a0.y+b0.y)*y0.y + (a0.z+b0.z)*y0.z + (a0.w+b0.w)*y0.w;
        iv += (a1.x+b1.x)*y1.x + (a1.y+b1.y)*y1.y + (a1.z+b1.z)*y1.z + (a1.w+b1.w)*y1.w;
        iv += (a2.x+b2.x)*y2.x + (a2.y+b2.y)*y2.y + (a2.z+b2.z)*y2.z + (a2.w+b2.w)*y2.w;
        iv += (a3.x+b3.x)*y3.x + (a3.y+b3.y)*y3.y + (a3.z+b3.z)*y3.z + (a3.w+b3.w)*y3.w;
        inv1 = iv;
    }
    float q0 = inv0 * g_Re[(size_t)e*32 + lane];
    float q1 = inv1 * g_Re[(size_t)EE*32 + (size_t)e*32 + lane];

    u64 a00 = 0ull, a01 = 0ull, a10 = 0ull, a11 = 0ull;
    #pragma unroll
    for (int c = 0; c < 32; c++) {
        u64 b0 = pk2(__shfl_sync(0xFFFFFFFFu, q0, c));
        u64 b1 = pk2(__shfl_sync(0xFFFFFFFFu, q1, c));
        const u64* w0 = (const u64*)&s_we[c*100];
        const u64* w1 = (const u64*)&s_we[3200 + c*100];
        a00 = fma2(b0, w0[lane], a00);
        a10 = fma2(b1, w1[lane], a10);
        if (lane < 18) {
            a01 = fma2(b0, w0[lane + 32], a01);
            a11 = fma2(b1, w1[lane + 32], a11);
        }
    }
    // pair p = lane  (outputs j = 2p, 2p+1)
    {
        float2 v0 = u2f(a00), v1 = u2f(a10);
        *(float2*)&out[6000000 + e*100 + 2*lane] = make_float2(v0.x + v1.x, v0.y + v1.y);
        *(float4*)&out[38000000 + e*200 + 4*lane] = make_float4(v0.x, v1.x, v0.y, v1.y);
    }
    // pair p = lane+32 (outputs j = 64+2*lane, 65+2*lane) for lane < 18
    if (lane < 18) {
        float2 v0 = u2f(a01), v1 = u2f(a11);
        *(float2*)&out[6000000 + e*100 + 64 + 2*lane] = make_float2(v0.x + v1.x, v0.y + v1.y);
        *(float4*)&out[38000000 + e*200 + 128 + 4*lane] = make_float4(v0.x, v1.x, v0.y, v1.y);
    }
}

// ---------------- launch ----------------
extern "C" void kernel_launch(void* const* d_in, const int* in_sizes, int n_in,
                              void* d_out, int out_size) {
    const float* positions = (const float*)d_in[0];
    const float* shifts    = (const float*)d_in[2];
    const float* W_emb     = (const float*)d_in[3];
    const float* rW1       = (const float*)d_in[4];
    const float* rb1       = (const float*)d_in[5];
    const float* rW2       = (const float*)d_in[6];
    const float* rb2       = (const float*)d_in[7];
    const float* rW3       = (const float*)d_in[8];
    const float* W_up      = (const float*)d_in[9];
    const float* W_lmix    = (const float*)d_in[10];
    const float* W_scm     = (const float*)d_in[11];
    const float* gsc       = (const float*)d_in[12];
    const float* W_prod    = (const float*)d_in[13];
    const float* W_hid     = (const float*)d_in[14];
    const float* W_node    = (const float*)d_in[15];
    const float* W_edge    = (const float*)d_in[16];
    const float* W_er      = (const float*)d_in[17];
    const int*   ei        = (const int*)d_in[18];
    const int*   nt        = (const int*)d_in[19];
    float* out = (float*)d_out;

    cudaFuncSetAttribute(k_radial, cudaFuncAttributeMaxDynamicSharedMemorySize, 52736);
    cudaFuncSetAttribute(k_node,   cudaFuncAttributeMaxDynamicSharedMemorySize, 66560);

    // Launch order arranged so k_radial(t=0) sits in the ncu capture slot
    // (my 4th launch). Dependencies: k_radial needs only g_eb (k_geom);
    // k_sort before k_node; k_init before k_h0.
    k_zero<<<(NN + 255) / 256, 256>>>();
    k_geom<<<EE / 256, 256>>>(positions, shifts, ei);
    k_init<<<(NN * 128 + 255) / 256, 256>>>(W_emb, nt);
    k_radial<<<EE / 128, 128, 52736>>>(rW1, rb1, rW2, rb2, rW3, W_er, 0);
    k_sort<<<(NN + 127) / 128, 128>>>();
    k_h0<<<NN / 4, 128>>>(W_up, 0, 0);
    k_node<<<NN / 8, 256, 66560>>>(W_lmix, W_scm, W_hid, gsc, W_prod, W_node,
                                   ei, nt, 0, 0);
    k_radial<<<EE / 128, 128, 52736>>>(rW1, rb1, rW2, rb2, rW3, W_er, 1);
    k_h0<<<NN / 4, 128>>>(W_up, 1, 1);
    k_node<<<NN / 8, 256, 66560>>>(W_lmix, W_scm, W_hid, gsc, W_prod, W_node,
                                   ei, nt, 1, 1);
    k_fin_node<<<(NN * 50 + 255) / 256, 256>>>(out);
    k_fin_edge<<<EE / 8, 256>>>(W_edge, ei, out);
}

// round 12
// speedup vs baseline: 1.7846x; 1.0601x over previous
#include <cuda_runtime.h>
#include <math.h>

#define NN 20000
#define EE 320000
#define NEL 10
#define BUCKET 128

typedef unsigned long long u64;

// ---------------- f32x2 helpers (Blackwell packed fp32) ----------------
__device__ __forceinline__ u64 pk2(float v) {
    u64 r; asm("mov.b64 %0, {%1, %1};" : "=l"(r) : "f"(v)); return r;
}
__device__ __forceinline__ u64 fma2(u64 a, u64 b, u64 c) {
    u64 d; asm("fma.rn.f32x2 %0, %1, %2, %3;" : "=l"(d) : "l"(a), "l"(b), "l"(c)); return d;
}
__device__ __forceinline__ float2 u2f(u64 v) {
    float2 o; asm("mov.b64 {%0, %1}, %2;" : "=f"(o.x), "=f"(o.y) : "l"(v)); return o;
}
// fast silu: __expf (2-3 ulp at our small args) + approx divide (2 ulp).
// ~6 instr vs ~28 for accurate expf + IEEE div. Error class ~2e-7 relative —
// fp32-rounding territory; the R6 failure was the sin recurrence, not exp.
__device__ __forceinline__ float silu(float x) {
    return __fdividef(x, 1.0f + __expf(-x));
}

// ---------------- scratch (static device globals; no allocation) ----------------
__device__ __align__(256) float g_Y[EE * 16];
__device__ __align__(256) float g_eb[EE * 8];
__device__ __align__(256) float g_R[(size_t)EE * 128];
__device__ __align__(256) float g_Re[(size_t)2 * EE * 32];   // per-layer Re
__device__ __align__(256) float g_nfA[NN * 512];
__device__ __align__(256) float g_nfB[NN * 512];
__device__ __align__(256) float g_h0[NN * 32];
__device__ int   g_cnt[NN];
__device__ int   g_bucket[NN * BUCKET];
__device__ __align__(256) float g_ncs0[NN * 100];
__device__ __align__(256) float g_ncs1[NN * 100];

__device__ constexpr int OF[16] = {0,1,1,1,2,2,2,2,2,3,3,3,3,3,3,3};

// ---------------- setup kernels ----------------
__global__ void k_zero() {
    int i = blockIdx.x * 256 + threadIdx.x;
    if (i < NN) g_cnt[i] = 0;
}

__global__ void k_geom(const float* __restrict__ pos, const float* __restrict__ shifts,
                       const int* __restrict__ ei) {
    int e = blockIdx.x * 256 + threadIdx.x;
    if (e >= EE) return;
    int src = ei[e], dst = ei[EE + e];
    float vx = pos[dst*3+0] - pos[src*3+0] + shifts[e*3+0];
    float vy = pos[dst*3+1] - pos[src*3+1] + shifts[e*3+1];
    float vz = pos[dst*3+2] - pos[src*3+2] + shifts[e*3+2];
    float r = sqrtf(vx*vx + vy*vy + vz*vz) + 1e-9f;
    float inv = 1.0f / r;
    float x = vx*inv, y = vy*inv, z = vz*inv;
    const float s3 = 1.7320508075688772f, s5 = 2.23606797749979f;
    const float s15 = 3.872983346207417f, s7 = 2.6457513110645907f;
    const float c358 = 2.091650066335189f, c105 = 10.246950765959598f, c218 = 1.6201851746019651f;
    float z2 = z*z, x2 = x*x, y2 = y*y;
    float4* Yo = (float4*)(g_Y + e*16);
    Yo[0] = make_float4(1.0f, s3*x, s3*y, s3*z);
    Yo[1] = make_float4(s15*x*y, s15*y*z, 0.5f*s5*(3.0f*z2-1.0f), s15*x*z);
    Yo[2] = make_float4(0.5f*s15*(x2-y2), c358*y*(3.0f*x2-y2), c105*x*y*z,
                        c218*y*(5.0f*z2-1.0f));
    Yo[3] = make_float4(0.5f*s7*z*(5.0f*z2-3.0f), c218*x*(5.0f*z2-1.0f),
                        0.5f*c105*z*(x2-y2), c358*x*(x2-3.0f*y2));
    // bessel * polynomial cutoff (P=5)
    float xr = r * 0.2f;
    float fc = 0.0f;
    if (xr < 1.0f) {
        float p2 = xr*xr, p4 = p2*p2, p5 = p4*xr;
        fc = 1.0f - 21.0f*p5 + 35.0f*p5*xr - 15.0f*p5*p2;
    }
    float s = 0.6324555320336759f * inv * fc;
    // accurate sinf per harmonic (matches reference jnp.sin)
    float eb[8];
    #pragma unroll
    for (int n = 1; n <= 8; n++)
        eb[n-1] = s * sinf((float)n * 0.6283185307179586f * r);
    float4* ebo = (float4*)(g_eb + e*8);
    ebo[0] = make_float4(eb[0], eb[1], eb[2], eb[3]);
    ebo[1] = make_float4(eb[4], eb[5], eb[6], eb[7]);
    // bucket scatter (dst)
    int p = atomicAdd(&g_cnt[dst], 1);
    if (p < BUCKET) g_bucket[dst*BUCKET + p] = e;
}

__global__ void k_sort() {  // deterministic order: per-node insertion sort by edge id
    int n = blockIdx.x * 128 + threadIdx.x;
    if (n >= NN) return;
    int deg = g_cnt[n]; if (deg > BUCKET) deg = BUCKET;
    int* b = g_bucket + n*BUCKET;
    for (int i = 1; i < deg; i++) {
        int v = b[i]; int j = i - 1;
        while (j >= 0 && b[j] > v) { b[j+1] = b[j]; j--; }
        b[j+1] = v;
    }
}

__global__ void k_init(const float* __restrict__ W_emb, const int* __restrict__ nt) {
    int idx = blockIdx.x * 256 + threadIdx.x;   // float4 index
    if (idx >= NN * 128) return;
    int n = idx >> 7, rem = idx & 127, c = rem >> 2, l4 = rem & 3;
    float4 v = make_float4(0.0f, 0.0f, 0.0f, 0.0f);
    if (l4 == 0) v.x = W_emb[nt[n]*32 + c];
    ((float4*)g_nfA)[idx] = v;
}

// ---------------- per-layer kernels ----------------
__global__ void k_h0(const float* __restrict__ W_up, int t, int flip) {
    int w = threadIdx.x >> 5, lane = threadIdx.x & 31;
    int n = blockIdx.x * 4 + w;
    if (n >= NN) return;
    const float* nfin = flip ? g_nfB : g_nfA;
    const float* nf0 = nfin + n*512;
    const float* W = W_up + t*1024;
    float a = 0.0f;
    #pragma unroll
    for (int c = 0; c < 32; c++) a += nf0[c*16] * W[c*32 + lane];
    g_h0[n*32 + lane] = a;
}

// fused radial MLP: eb -> silu(W1) -> silu(W2) -> W3 -> R ; plus Re = silu(eb@W_er)
// one edge per thread, f32x2-packed over output-channel pairs.
// (R9-measured structure; only silu impl changed this round.)
__global__ void __launch_bounds__(128) k_radial(
        const float* __restrict__ rW1, const float* __restrict__ rb1,
        const float* __restrict__ rW2, const float* __restrict__ rb2,
        const float* __restrict__ rW3, const float* __restrict__ W_er, int t) {
    extern __shared__ float sw[];
    float* s_w1  = sw;            // 512
    float* s_b1  = sw + 512;      // 64
    float* s_w2  = sw + 576;      // 4096  (16B-aligned: 576*4=2304)
    float* s_b2  = sw + 4672;     // 64
    float* s_w3  = sw + 4736;     // 8192  (16B-aligned: 4736*4=18944)
    float* s_wer = sw + 12928;    // 256   -> total 13184 floats = 52736 B
    int tid = threadIdx.x;
    for (int i = tid; i < 512;  i += 128) s_w1[i]  = rW1[t*512 + i];
    for (int i = tid; i < 4096; i += 128) s_w2[i]  = rW2[t*4096 + i];
    for (int i = tid; i < 8192; i += 128) s_w3[i]  = rW3[t*8192 + i];
    for (int i = tid; i < 256;  i += 128) s_wer[i] = W_er[t*256 + i];
    if (tid < 64) { s_b1[tid] = rb1[t*64 + tid]; s_b2[tid] = rb2[t*64 + tid]; }
    __syncthreads();

    int e = blockIdx.x * 128 + tid;
    float4 ebA = *(const float4*)&g_eb[e*8];
    float4 ebB = *(const float4*)&g_eb[e*8 + 4];
    float ebv[8] = {ebA.x, ebA.y, ebA.z, ebA.w, ebB.x, ebB.y, ebB.z, ebB.w};
    u64 ebp[8];
    #pragma unroll
    for (int b = 0; b < 8; b++) ebp[b] = pk2(ebv[b]);

    // ---- layer 1: 8 -> 64, silu ----
    float x1s[64];
    const u64* w1p = (const u64*)s_w1;
    #pragma unroll 8
    for (int jp = 0; jp < 32; jp++) {
        u64 acc = *(const u64*)&s_b1[2*jp];
        #pragma unroll
        for (int b = 0; b < 8; b++) acc = fma2(ebp[b], w1p[b*32 + jp], acc);
        float2 v = u2f(acc);
        x1s[2*jp]   = silu(v.x);
        x1s[2*jp+1] = silu(v.y);
    }

    // ---- layer 2: 64 -> 64, silu ----
    u64 acc2[32];
    #pragma unroll
    for (int jq = 0; jq < 32; jq++) acc2[jq] = *(const u64*)&s_b2[2*jq];
    const ulonglong2* w2p = (const ulonglong2*)s_w2;
    #pragma unroll 4
    for (int i = 0; i < 64; i++) {
        u64 bc = pk2(x1s[i]);
        #pragma unroll
        for (int jq = 0; jq < 16; jq++) {
            ulonglong2 wv = w2p[i*16 + jq];
            acc2[2*jq]   = fma2(bc, wv.x, acc2[2*jq]);
            acc2[2*jq+1] = fma2(bc, wv.y, acc2[2*jq+1]);
        }
    }
    float x2s[64];
    #pragma unroll 8
    for (int jq = 0; jq < 32; jq++) {
        float2 v = u2f(acc2[jq]);
        x2s[2*jq]   = silu(v.x);
        x2s[2*jq+1] = silu(v.y);
    }

    // ---- layer 3: 64 -> 128 (no act), two halves for register pressure ----
    float* Rp = g_R + (size_t)e * 128;
    const ulonglong2* w3p = (const ulonglong2*)s_w3;
    #pragma unroll
    for (int h = 0; h < 2; h++) {
        u64 acc3[32];
        #pragma unroll
        for (int q = 0; q < 32; q++) acc3[q] = 0ull;
        #pragma unroll 4
        for (int i = 0; i < 64; i++) {
            u64 bc = pk2(x2s[i]);
            #pragma unroll
            for (int q = 0; q < 16; q++) {
                ulonglong2 wv = w3p[i*32 + h*16 + q];
                acc3[2*q]   = fma2(bc, wv.x, acc3[2*q]);
                acc3[2*q+1] = fma2(bc, wv.y, acc3[2*q+1]);
            }
        }
        #pragma unroll
        for (int q = 0; q < 16; q++) {
            ulonglong2 st; st.x = acc3[2*q]; st.y = acc3[2*q+1];
            *(ulonglong2*)&Rp[h*64 + 4*q] = st;
        }
    }

    // ---- Re = silu(eb @ W_er) : 8 -> 32, per-layer buffer ----
    float* ReOut = g_Re + (size_t)t * EE * 32;
    const u64* werp = (const u64*)s_wer;
    #pragma unroll 4
    for (int cp = 0; cp < 16; cp++) {
        u64 acc = 0ull;
        #pragma unroll
        for (int b = 0; b < 8; b++) acc = fma2(ebp[b], werp[b*16 + cp], acc);
        float2 v = u2f(acc);
        float2 o; o.x = silu(v.x); o.y = silu(v.y);
        *(float2*)&ReOut[e*32 + 2*cp] = o;
    }
}

// fused per-node: gather/agg -> m -> sc -> pf -> nf_new -> node head (8 nodes/block)
__global__ void k_node(const float* __restrict__ W_lmix, const float* __restrict__ W_scm,
                       const float* __restrict__ W_hid, const float* __restrict__ gsc,
                       const float* __restrict__ W_prod, const float* __restrict__ W_node,
                       const int* __restrict__ ei, const int* __restrict__ ntypes,
                       int t, int flip) {
    extern __shared__ float sm[];
    float* s_lmix = sm;                 // 4096
    float* s_scm  = sm + 4096;          // 4096
    float* s_hid  = sm + 8192;          // 4096
    float* s_buf  = sm + 12288;         // 8 warps * 512
    float* s_q    = sm + 12288 + 4096;  // 8 warps * 32
    int tid = threadIdx.x;
    for (int i = tid; i < 4096; i += 256) {
        s_lmix[i] = W_lmix[t*4096 + i];
        s_scm[i]  = W_scm[t*4096 + i];
        s_hid[i]  = W_hid[t*4096 + i];
    }
    __syncthreads();
    int w = tid >> 5, lane = tid & 31;
    int n = blockIdx.x * 8 + w;
    if (n >= NN) return;
    const float* nfin = flip ? g_nfB : g_nfA;
    float* nfout = flip ? g_nfA : g_nfB;
    float* ncs = t ? g_ncs1 : g_ncs0;
    float* sb = s_buf + w*512;

    // phase A: gather aggregation (lane = channel c).
    float acc[16];
    #pragma unroll
    for (int l = 0; l < 16; l++) acc[l] = 0.0f;
    int deg = g_cnt[n]; if (deg > BUCKET) deg = BUCKET;
    const int* bk = g_bucket + n*BUCKET;
    int eReg[4], sReg[4];
    #pragma unroll
    for (int q = 0; q < 4; q++) {
        int idx = q*32 + lane;
        int ev = (idx < deg) ? bk[idx] : 0;
        eReg[q] = ev;
        sReg[q] = (idx < deg) ? ei[ev] : 0;
    }
    #pragma unroll
    for (int q = 0; q < 4; q++) {
        int lim = deg - q*32;
        if (lim <= 0) break;
        if (lim > 32) lim = 32;
        for (int sl = 0; sl < lim; sl++) {
            int e   = __shfl_sync(0xFFFFFFFFu, eReg[q], sl);
            int src = __shfl_sync(0xFFFFFFFFu, sReg[q], sl);
            float h = g_h0[src*32 + lane];
            const float* Rp = g_R + (size_t)e * 128;
            float r0 = Rp[lane]*h, r1 = Rp[32+lane]*h, r2 = Rp[64+lane]*h, r3 = Rp[96+lane]*h;
            const float4* Yv = (const float4*)(g_Y + e*16);
            float4 y0 = Yv[0], y1 = Yv[1], y2 = Yv[2], y3 = Yv[3];
            acc[0]  += r0*y0.x;
            acc[1]  += r1*y0.y;  acc[2]  += r1*y0.z;  acc[3]  += r1*y0.w;
            acc[4]  += r2*y1.x;  acc[5]  += r2*y1.y;  acc[6]  += r2*y1.z;
            acc[7]  += r2*y1.w;  acc[8]  += r2*y2.x;
            acc[9]  += r3*y2.y;  acc[10] += r3*y2.z;  acc[11] += r3*y2.w;
            acc[12] += r3*y3.x;  acc[13] += r3*y3.y;  acc[14] += r3*y3.z;
            acc[15] += r3*y3.w;
        }
    }
    #pragma unroll
    for (int l = 0; l < 16; l++) sb[l*32 + lane] = acc[l] * 0.0625f;
    __syncwarp();

    // phase B: m = agg mixed by W_lmix (lane = output k)
    float m[16];
    #pragma unroll
    for (int l = 0; l < 16; l++) {
        const float* wp = s_lmix + OF[l]*1024;
        float a = 0.0f;
        #pragma unroll
        for (int c = 0; c < 32; c++) a += sb[l*32 + c] * wp[c*32 + lane];
        m[l] = a;
    }
    __syncwarp();

    // phase C: sc from old nf (transpose into sb, then mix by W_scm * g_sc)
    {
        const float* nfo = nfin + n*512 + lane*16;
        float4 v0 = ((const float4*)nfo)[0];
        float4 v1 = ((const float4*)nfo)[1];
        float4 v2 = ((const float4*)nfo)[2];
        float4 v3 = ((const float4*)nfo)[3];
        sb[0*32+lane]=v0.x;  sb[1*32+lane]=v0.y;  sb[2*32+lane]=v0.z;  sb[3*32+lane]=v0.w;
        sb[4*32+lane]=v1.x;  sb[5*32+lane]=v1.y;  sb[6*32+lane]=v1.z;  sb[7*32+lane]=v1.w;
        sb[8*32+lane]=v2.x;  sb[9*32+lane]=v2.y;  sb[10*32+lane]=v2.z; sb[11*32+lane]=v2.w;
        sb[12*32+lane]=v3.x; sb[13*32+lane]=v3.y; sb[14*32+lane]=v3.z; sb[15*32+lane]=v3.w;
    }
    __syncwarp();
    int ty = ntypes[n];
    float g = gsc[t*NEL*32 + ty*32 + lane];
    float sc[16];
    #pragma unroll
    for (int l = 0; l < 16; l++) {
        const float* wp = s_scm + OF[l]*1024;
        float a = 0.0f;
        #pragma unroll
        for (int c = 0; c < 32; c++) a += sb[l*32 + c] * wp[c*32 + lane];
        sc[l] = a * g;
    }
    __syncwarp();

    // phase D: pf (lane = channel c)
    const float* wpp = W_prod + t*NEL*96 + ty*96;
    float w0 = wpp[lane], w1 = wpp[32+lane], w2 = wpp[64+lane];
    float s0 = m[0];
    float f = w0 + s0*w1 + s0*s0*w2;
    #pragma unroll
    for (int l = 0; l < 16; l++) sb[l*32 + lane] = m[l] * f;
    __syncwarp();

    // phase E: nf_new (lane = output k)
    float nfn[16];
    #pragma unroll
    for (int l = 0; l < 16; l++) {
        const float* wp = s_hid + OF[l]*1024;
        float a = 0.0f;
        #pragma unroll
        for (int c = 0; c < 32; c++) a += sb[l*32 + c] * wp[c*32 + lane];
        nfn[l] = a + sc[l];
    }
    float* nout = nfout + n*512 + lane*16;
    ((float4*)nout)[0] = make_float4(nfn[0],  nfn[1],  nfn[2],  nfn[3]);
    ((float4*)nout)[1] = make_float4(nfn[4],  nfn[5],  nfn[6],  nfn[7]);
    ((float4*)nout)[2] = make_float4(nfn[8],  nfn[9],  nfn[10], nfn[11]);
    ((float4*)nout)[3] = make_float4(nfn[12], nfn[13], nfn[14], nfn[15]);

    // phase F: node head (new nf L=0 @ W_node)
    s_q[w*32 + lane] = nfn[0];
    __syncwarp();
    const float* Wn = W_node + t*3200;
    for (int j = lane; j < 100; j += 32) {
        float a = 0.0f;
        #pragma unroll
        for (int c = 0; c < 32; c++) a += s_q[w*32 + c] * Wn[c*100 + j];
        ncs[n*100 + j] = a;
    }
}

// ---------------- output assembly ----------------
// out layout: [node_sum N*100][node_contrib N*100*2][edge_sum E*100][edge_contrib E*100*2]
__global__ void k_fin_node(float* __restrict__ out) {
    int i2 = blockIdx.x * 256 + threadIdx.x;   // pair index
    if (i2 >= NN * 50) return;
    float2 a = *(const float2*)&g_ncs0[2*i2];
    float2 b = *(const float2*)&g_ncs1[2*i2];
    *(float2*)&out[2*i2] = make_float2(a.x + b.x, a.y + b.y);
    *(float4*)&out[2000000 + 4*i2] = make_float4(a.x, b.x, a.y, b.y);
}

// fused edge head, both layers: invariant q = Re * <nf_src+nf_dst, Y> computed
// directly from the live nf buffers (layer0 -> g_nfB, layer1 -> g_nfA), then
// 32->100 projection + sum + interleaved contrib. Warp per edge; f32x2 pairs.
__global__ void k_fin_edge(const float* __restrict__ W_edge, const int* __restrict__ ei,
                           float* __restrict__ out) {
    __shared__ float s_we[6528];   // 2*3200 used, padded
    int tid = threadIdx.x;
    for (int i = tid; i < 6400; i += 256) s_we[i] = W_edge[i];  // [t][c][j]
    __syncthreads();
    int w = tid >> 5, lane = tid & 31;
    int e = blockIdx.x * 8 + w;
    int src = ei[e], dst = ei[EE + e];
    const float4* Yv = (const float4*)(g_Y + e*16);
    float4 y0 = Yv[0], y1 = Yv[1], y2 = Yv[2], y3 = Yv[3];

    float inv0, inv1;
    {   // layer 0 output lives in g_nfB
        const float* ns = g_nfB + src*512 + lane*16;
        const float* nd = g_nfB + dst*512 + lane*16;
        float4 a0 = ((const float4*)ns)[0], b0 = ((const float4*)nd)[0];
        float4 a1 = ((const float4*)ns)[1], b1 = ((const float4*)nd)[1];
        float4 a2 = ((const float4*)ns)[2], b2 = ((const float4*)nd)[2];
        float4 a3 = ((const float4*)ns)[3], b3 = ((const float4*)nd)[3];
        float iv = 0.0f;
        iv += (a0.x+b0.x)*y0.x + (a0.y+b0.y)*y0.y + (a0.z+b0.z)*y0.z + (a0.w+b0.w)*y0.w;
        iv += (a1.x+b1.x)*y1.x + (a1.y+b1.y)*y1.y + (a1.z+b1.z)*y1.z + (a1.w+b1.w)*y1.w;
        iv += (a2.x+b2.x)*y2.x + (a2.y+b2.y)*y2.y + (a2.z+b2.z)*y2.z + (a2.w+b2.w)*y2.w;
        iv += (a3.x+b3.x)*y3.x + (a3.y+b3.y)*y3.y + (a3.z+b3.z)*y3.z + (a3.w+b3.w)*y3.w;
        inv0 = iv;
    }
    {   // layer 1 output lives in g_nfA
        const float* ns = g_nfA + src*512 + lane*16;
        const float* nd = g_nfA + dst*512 + lane*16;
        float4 a0 = ((const float4*)ns)[0], b0 = ((const float4*)nd)[0];
        float4 a1 = ((const float4*)ns)[1], b1 = ((const float4*)nd)[1];
        float4 a2 = ((const float4*)ns)[2], b2 = ((const float4*)nd)[2];
        float4 a3 = ((const float4*)ns)[3], b3 = ((const float4*)nd)[3];
        float iv = 0.0f;
        iv += (a0.x+b0.x)*y0.x + (a0.y+b0.y)*y0.y + (a0.z+b0.z)*y0.z + (a0.w+b0.w)*y0.w;
        iv += (a1.x+b1.x)*y1.x + (a1.y+b1.y)*y1.y + (a1.z+b1.z)*y1.z + (a1.w+b1.w)*y1.w;
        iv += (a2.x+b2.x)*y2.x + (a2.y+b2.y)*y2.y + (a2.z+b2.z)*y2.z + (a2.w+b2.w)*y2.w;
        iv += (a3.x+b3.x)*y3.x + (a3.y+b3.y)*y3.y + (a3.z+b3.z)*y3.z + (a3.w+b3.w)*y3.w;
        inv1 = iv;
    }
    float q0 = inv0 * g_Re[(size_t)e*32 + lane];
    float q1 = inv1 * g_Re[(size_t)EE*32 + (size_t)e*32 + lane];

    u64 a00 = 0ull, a01 = 0ull, a10 = 0ull, a11 = 0ull;
    #pragma unroll
    for (int c = 0; c < 32; c++) {
        u64 b0 = pk2(__shfl_sync(0xFFFFFFFFu, q0, c));
        u64 b1 = pk2(__shfl_sync(0xFFFFFFFFu, q1, c));
        const u64* w0 = (const u64*)&s_we[c*100];
        const u64* w1 = (const u64*)&s_we[3200 + c*100];
        a00 = fma2(b0, w0[lane], a00);
        a10 = fma2(b1, w1[lane], a10);
        if (lane < 18) {
            a01 = fma2(b0, w0[lane + 32], a01);
            a11 = fma2(b1, w1[lane + 32], a11);
        }
    }
    // pair p = lane  (outputs j = 2p, 2p+1)
    {
        float2 v0 = u2f(a00), v1 = u2f(a10);
        *(float2*)&out[6000000 + e*100 + 2*lane] = make_float2(v0.x + v1.x, v0.y + v1.y);
        *(float4*)&out[38000000 + e*200 + 4*lane] = make_float4(v0.x, v1.x, v0.y, v1.y);
    }
    // pair p = lane+32 (outputs j = 64+2*lane, 65+2*lane) for lane < 18
    if (lane < 18) {
        float2 v0 = u2f(a01), v1 = u2f(a11);
        *(float2*)&out[6000000 + e*100 + 64 + 2*lane] = make_float2(v0.x + v1.x, v0.y + v1.y);
        *(float4*)&out[38000000 + e*200 + 128 + 4*lane] = make_float4(v0.x, v1.x, v0.y, v1.y);
    }
}

// ---------------- launch ----------------
extern "C" void kernel_launch(void* const* d_in, const int* in_sizes, int n_in,
                              void* d_out, int out_size) {
    const float* positions = (const float*)d_in[0];
    const float* shifts    = (const float*)d_in[2];
    const float* W_emb     = (const float*)d_in[3];
    const float* rW1       = (const float*)d_in[4];
    const float* rb1       = (const float*)d_in[5];
    const float* rW2       = (const float*)d_in[6];
    const float* rb2       = (const float*)d_in[7];
    const float* rW3       = (const float*)d_in[8];
    const float* W_up      = (const float*)d_in[9];
    const float* W_lmix    = (const float*)d_in[10];
    const float* W_scm     = (const float*)d_in[11];
    const float* gsc       = (const float*)d_in[12];
    const float* W_prod    = (const float*)d_in[13];
    const float* W_hid     = (const float*)d_in[14];
    const float* W_node    = (const float*)d_in[15];
    const float* W_edge    = (const float*)d_in[16];
    const float* W_er      = (const float*)d_in[17];
    const int*   ei        = (const int*)d_in[18];
    const int*   nt        = (const int*)d_in[19];
    float* out = (float*)d_out;

    cudaFuncSetAttribute(k_radial, cudaFuncAttributeMaxDynamicSharedMemorySize, 52736);
    cudaFuncSetAttribute(k_node,   cudaFuncAttributeMaxDynamicSharedMemorySize, 66560);

    // Launch order keeps k_radial(t=0) in the ncu capture slot (4th launch)
    // for direct A/B against R11's 473.9us measurement.
    k_zero<<<(NN + 255) / 256, 256>>>();
    k_geom<<<EE / 256, 256>>>(positions, shifts, ei);
    k_init<<<(NN * 128 + 255) / 256, 256>>>(W_emb, nt);
    k_radial<<<EE / 128, 128, 52736>>>(rW1, rb1, rW2, rb2, rW3, W_er, 0);
    k_sort<<<(NN + 127) / 128, 128>>>();
    k_h0<<<NN / 4, 128>>>(W_up, 0, 0);
    k_node<<<NN / 8, 256, 66560>>>(W_lmix, W_scm, W_hid, gsc, W_prod, W_node,
                                   ei, nt, 0, 0);
    k_radial<<<EE / 128, 128, 52736>>>(rW1, rb1, rW2, rb2, rW3, W_er, 1);
    k_h0<<<NN / 4, 128>>>(W_up, 1, 1);
    k_node<<<NN / 8, 256, 66560>>>(W_lmix, W_scm, W_hid, gsc, W_prod, W_node,
                                   ei, nt, 1, 1);
    k_fin_node<<<(NN * 50 + 255) / 256, 256>>>(out);
    k_fin_edge<<<EE / 8, 256>>>(W_edge, ei, out);
}